// round 1
// baseline (speedup 1.0000x reference)
#include <cuda_runtime.h>
#include <cuda_bf16.h>

// SR-GNN forward. Shapes (fixed by problem):
//   B=1024, N=50, S=50, H=128, V=100000
#define Bb 1024
#define Nn 50
#define Ss 50
#define Hh 128
#define Vv 100000

// ---------------- scratch (device globals; no allocation allowed) ----------
__device__ float g_h     [Bb * Nn * Hh];          // emb[items]
__device__ float g_hin   [Bb * Nn * Hh];          // h @ ein_w.T + ein_b
__device__ float g_hout  [Bb * Nn * Hh];          // h @ eou_w.T + eou_b
__device__ float g_inputs[Bb * Nn * 2 * Hh];      // [a_in | a_out]
__device__ float g_gi    [Bb * Nn * 3 * Hh];
__device__ float g_gh    [Bb * Nn * 3 * Hh];
__device__ float g_newh  [Bb * Nn * Hh];
__device__ float g_seqh  [Bb * Ss * Hh];
__device__ float g_ht    [Bb * Hh];
__device__ float g_q1    [Bb * Hh];
__device__ float g_q2    [Bb * Ss * Hh];
__device__ float g_avec  [Bb * Hh];

// ---------------- generic tiled SGEMM: C[M,N] = A[M,K] @ W[N,K]^T (+bias) --
// 64x64 tile, BK=16, 256 threads, 4x4 register micro-tile, float4 loads.
__global__ void sgemm_bias_kernel(const float* __restrict__ A,
                                  const float* __restrict__ W,
                                  const float* __restrict__ bias,
                                  float* __restrict__ C,
                                  int M, int N, int K) {
    __shared__ __align__(16) float As[16][64];
    __shared__ __align__(16) float Ws[16][64];

    const int tid = threadIdx.x;
    const int tx = tid & 15;        // 0..15 -> output cols (x4)
    const int ty = tid >> 4;        // 0..15 -> output rows (x4)
    const int rM = blockIdx.y * 64;
    const int cN = blockIdx.x * 64;

    const int lrow = tid >> 2;      // 0..63 (tile row loaded by this thread)
    const int lkq  = tid & 3;       // 0..3  (which float4 along BK)

    float acc[4][4];
#pragma unroll
    for (int i = 0; i < 4; i++)
#pragma unroll
        for (int j = 0; j < 4; j++) acc[i][j] = 0.f;

    for (int kt = 0; kt < K; kt += 16) {
        float4 av = make_float4(0.f, 0.f, 0.f, 0.f);
        float4 wv = make_float4(0.f, 0.f, 0.f, 0.f);
        int gr = rM + lrow;
        if (gr < M) av = *(const float4*)(A + (size_t)gr * K + kt + lkq * 4);
        int gw = cN + lrow;
        if (gw < N) wv = *(const float4*)(W + (size_t)gw * K + kt + lkq * 4);

        As[lkq * 4 + 0][lrow] = av.x;
        As[lkq * 4 + 1][lrow] = av.y;
        As[lkq * 4 + 2][lrow] = av.z;
        As[lkq * 4 + 3][lrow] = av.w;
        Ws[lkq * 4 + 0][lrow] = wv.x;
        Ws[lkq * 4 + 1][lrow] = wv.y;
        Ws[lkq * 4 + 2][lrow] = wv.z;
        Ws[lkq * 4 + 3][lrow] = wv.w;
        __syncthreads();

#pragma unroll
        for (int k = 0; k < 16; k++) {
            float4 ra = *(const float4*)&As[k][ty * 4];
            float4 rw = *(const float4*)&Ws[k][tx * 4];
            acc[0][0] += ra.x * rw.x; acc[0][1] += ra.x * rw.y;
            acc[0][2] += ra.x * rw.z; acc[0][3] += ra.x * rw.w;
            acc[1][0] += ra.y * rw.x; acc[1][1] += ra.y * rw.y;
            acc[1][2] += ra.y * rw.z; acc[1][3] += ra.y * rw.w;
            acc[2][0] += ra.z * rw.x; acc[2][1] += ra.z * rw.y;
            acc[2][2] += ra.z * rw.z; acc[2][3] += ra.z * rw.w;
            acc[3][0] += ra.w * rw.x; acc[3][1] += ra.w * rw.y;
            acc[3][2] += ra.w * rw.z; acc[3][3] += ra.w * rw.w;
        }
        __syncthreads();
    }

#pragma unroll
    for (int i = 0; i < 4; i++) {
        int row = rM + ty * 4 + i;
        if (row >= M) continue;
#pragma unroll
        for (int j = 0; j < 4; j++) {
            int col = cN + tx * 4 + j;
            if (col < N) {
                float b = bias ? bias[col] : 0.f;
                C[(size_t)row * N + col] = acc[i][j] + b;
            }
        }
    }
}

// ---------------- h = emb[items] ------------------------------------------
__global__ void gather_kernel(const int* __restrict__ items,
                              const float* __restrict__ emb,
                              float* __restrict__ h, int total4) {
    int i = blockIdx.x * blockDim.x + threadIdx.x;
    if (i >= total4) return;
    int bn = i >> 5;          // /32 (H/4 = 32 float4 per row)
    int q  = i & 31;
    int it = items[bn];
    ((float4*)h)[i] = ((const float4*)emb)[(size_t)it * 32 + q];
}

// ---------------- batched small matmul with adjacency ----------------------
// inputs[b,n,0:H]   = A[b,:, :N] @ hin[b]  + b_iah
// inputs[b,n,H:2H]  = A[b,:, N:] @ hout[b] + b_oah
__global__ void amm_kernel(const float* __restrict__ Amat,
                           const float* __restrict__ hin,
                           const float* __restrict__ hout,
                           const float* __restrict__ b_iah,
                           const float* __restrict__ b_oah,
                           float* __restrict__ inputs) {
    int b = blockIdx.x;
    int tid = threadIdx.x;                 // 256 threads
    __shared__ float sA[Nn * Nn];          // 50x50
    __shared__ float sH[Nn * Hh];          // 50x128

    const float* Ab = Amat + (size_t)b * Nn * 2 * Nn;

    // ---- pass 1: a_in ----
    for (int i = tid; i < Nn * Nn; i += 256)
        sA[i] = Ab[(i / Nn) * (2 * Nn) + (i % Nn)];
    for (int i = tid; i < Nn * Hh; i += 256)
        sH[i] = hin[(size_t)b * Nn * Hh + i];
    __syncthreads();
    for (int o = tid; o < Nn * Hh; o += 256) {
        int n = o / Hh, hh = o % Hh;
        float acc = b_iah[hh];
#pragma unroll 10
        for (int k = 0; k < Nn; k++) acc += sA[n * Nn + k] * sH[k * Hh + hh];
        inputs[((size_t)b * Nn + n) * (2 * Hh) + hh] = acc;
    }
    __syncthreads();

    // ---- pass 2: a_out ----
    for (int i = tid; i < Nn * Nn; i += 256)
        sA[i] = Ab[(i / Nn) * (2 * Nn) + Nn + (i % Nn)];
    for (int i = tid; i < Nn * Hh; i += 256)
        sH[i] = hout[(size_t)b * Nn * Hh + i];
    __syncthreads();
    for (int o = tid; o < Nn * Hh; o += 256) {
        int n = o / Hh, hh = o % Hh;
        float acc = b_oah[hh];
#pragma unroll 10
        for (int k = 0; k < Nn; k++) acc += sA[n * Nn + k] * sH[k * Hh + hh];
        inputs[((size_t)b * Nn + n) * (2 * Hh) + Hh + hh] = acc;
    }
}

// ---------------- GRU gate math -------------------------------------------
__global__ void gru_kernel(const float* __restrict__ gi,
                           const float* __restrict__ gh,
                           const float* __restrict__ h,
                           float* __restrict__ newh, int total) {
    int i = blockIdx.x * blockDim.x + threadIdx.x;
    if (i >= total) return;
    int bn = i / Hh, hh = i - bn * Hh;
    size_t base = (size_t)bn * 3 * Hh;
    float i_r = gi[base + hh];
    float i_i = gi[base + Hh + hh];
    float i_n = gi[base + 2 * Hh + hh];
    float h_r = gh[base + hh];
    float h_i = gh[base + Hh + hh];
    float h_n = gh[base + 2 * Hh + hh];
    float r = 1.f / (1.f + expf(-(i_r + h_r)));
    float z = 1.f / (1.f + expf(-(i_i + h_i)));
    float ng = tanhf(i_n + r * h_n);
    newh[i] = ng + z * (h[i] - ng);
}

// ---------------- alias gather + ht ---------------------------------------
__global__ void seq_kernel(const int* __restrict__ alias,
                           const int* __restrict__ mask,
                           const float* __restrict__ newh,
                           float* __restrict__ seqh,
                           float* __restrict__ ht) {
    int b = blockIdx.x;
    int tid = threadIdx.x;                 // 256
    __shared__ int sal[Ss];
    __shared__ int slast;
    if (tid < Ss) sal[tid] = alias[b * Ss + tid];
    if (tid == 0) {
        int c = 0;
        for (int s = 0; s < Ss; s++) c += mask[b * Ss + s];
        slast = c - 1;
    }
    __syncthreads();

    const float4* src = (const float4*)newh + (size_t)b * Nn * (Hh / 4);
    float4* dst = (float4*)seqh + (size_t)b * Ss * (Hh / 4);
    for (int i = tid; i < Ss * (Hh / 4); i += 256) {
        int s = i >> 5;     // /32
        int q = i & 31;
        dst[i] = src[sal[s] * 32 + q];
    }
    if (tid < 32) {
        const float4* hrow = (const float4*)newh +
                             ((size_t)b * Nn + sal[slast]) * (Hh / 4);
        ((float4*)ht)[(size_t)b * (Hh / 4) + tid] = hrow[tid];
    }
}

// ---------------- attention readout ---------------------------------------
// alpha[b,s] = sigmoid(q1[b] + q2[b,s]) . fc3_w ;  a[b] = sum_s alpha*seqh*mask
__global__ void attn_kernel(const float* __restrict__ q1,
                            const float* __restrict__ q2,
                            const float* __restrict__ fc3_w,
                            const float* __restrict__ seqh,
                            const int* __restrict__ mask,
                            float* __restrict__ avec) {
    int b = blockIdx.x;
    int tid = threadIdx.x;                 // 128
    int warp = tid >> 5, lane = tid & 31;
    __shared__ float salpha[Ss];

    for (int s = warp; s < Ss; s += 4) {
        float part = 0.f;
        for (int hh = lane; hh < Hh; hh += 32) {
            float v = q1[(size_t)b * Hh + hh] + q2[((size_t)b * Ss + s) * Hh + hh];
            float sg = 1.f / (1.f + expf(-v));
            part += sg * fc3_w[hh];
        }
#pragma unroll
        for (int off = 16; off; off >>= 1)
            part += __shfl_down_sync(0xffffffffu, part, off);
        if (lane == 0) salpha[s] = part;
    }
    __syncthreads();

    int hh = tid;
    float acc = 0.f;
    for (int s = 0; s < Ss; s++) {
        float m = (float)mask[b * Ss + s];
        acc += salpha[s] * seqh[((size_t)b * Ss + s) * Hh + hh] * m;
    }
    avec[(size_t)b * Hh + hh] = acc;
}

// ---------------- launch ---------------------------------------------------
extern "C" void kernel_launch(void* const* d_in, const int* in_sizes, int n_in,
                              void* d_out, int out_size) {
    const int*   alias_inputs = (const int*)  d_in[0];
    const float* A            = (const float*)d_in[1];
    const int*   items        = (const int*)  d_in[2];
    const int*   mask         = (const int*)  d_in[3];
    const float* emb          = (const float*)d_in[4];
    const float* ein_w        = (const float*)d_in[5];
    const float* ein_b        = (const float*)d_in[6];
    const float* eou_w        = (const float*)d_in[7];
    const float* eou_b        = (const float*)d_in[8];
    const float* w_ih         = (const float*)d_in[9];
    const float* w_hh         = (const float*)d_in[10];
    const float* b_ih         = (const float*)d_in[11];
    const float* b_hh         = (const float*)d_in[12];
    const float* b_iah        = (const float*)d_in[13];
    const float* b_oah        = (const float*)d_in[14];
    const float* fc1_w        = (const float*)d_in[15];
    const float* fc1_b        = (const float*)d_in[16];
    const float* fc2_w        = (const float*)d_in[17];
    const float* fc2_b        = (const float*)d_in[18];
    const float* fc3_w        = (const float*)d_in[19];
    float* out = (float*)d_out;

    float *p_h, *p_hin, *p_hout, *p_inputs, *p_gi, *p_gh, *p_newh;
    float *p_seqh, *p_ht, *p_q1, *p_q2, *p_avec;
    cudaGetSymbolAddress((void**)&p_h,      g_h);
    cudaGetSymbolAddress((void**)&p_hin,    g_hin);
    cudaGetSymbolAddress((void**)&p_hout,   g_hout);
    cudaGetSymbolAddress((void**)&p_inputs, g_inputs);
    cudaGetSymbolAddress((void**)&p_gi,     g_gi);
    cudaGetSymbolAddress((void**)&p_gh,     g_gh);
    cudaGetSymbolAddress((void**)&p_newh,   g_newh);
    cudaGetSymbolAddress((void**)&p_seqh,   g_seqh);
    cudaGetSymbolAddress((void**)&p_ht,     g_ht);
    cudaGetSymbolAddress((void**)&p_q1,     g_q1);
    cudaGetSymbolAddress((void**)&p_q2,     g_q2);
    cudaGetSymbolAddress((void**)&p_avec,   g_avec);

    const int BN = Bb * Nn;                // 51200

    // 1. gather h = emb[items]
    {
        int total4 = BN * (Hh / 4);
        gather_kernel<<<(total4 + 255) / 256, 256>>>(items, emb, p_h, total4);
    }
    // 2,3. hin / hout
    {
        dim3 g((Hh + 63) / 64, (BN + 63) / 64);
        sgemm_bias_kernel<<<g, 256>>>(p_h, ein_w, ein_b, p_hin, BN, Hh, Hh);
        sgemm_bias_kernel<<<g, 256>>>(p_h, eou_w, eou_b, p_hout, BN, Hh, Hh);
    }
    // 4. gh = h @ w_hh.T + b_hh   (N=384)
    {
        dim3 g((3 * Hh + 63) / 64, (BN + 63) / 64);
        sgemm_bias_kernel<<<g, 256>>>(p_h, w_hh, b_hh, p_gh, BN, 3 * Hh, Hh);
    }
    // 5. inputs = [A_in@hin + b_iah | A_out@hout + b_oah]
    amm_kernel<<<Bb, 256>>>(A, p_hin, p_hout, b_iah, b_oah, p_inputs);
    // 6. gi = inputs @ w_ih.T + b_ih   (K=256, N=384)
    {
        dim3 g((3 * Hh + 63) / 64, (BN + 63) / 64);
        sgemm_bias_kernel<<<g, 256>>>(p_inputs, w_ih, b_ih, p_gi, BN, 3 * Hh, 2 * Hh);
    }
    // 7. GRU
    {
        int total = BN * Hh;
        gru_kernel<<<(total + 255) / 256, 256>>>(p_gi, p_gh, p_h, p_newh, total);
    }
    // 8. seq_h + ht
    seq_kernel<<<Bb, 256>>>(alias_inputs, mask, p_newh, p_seqh, p_ht);
    // 9. q1 = ht @ fc1_w.T + fc1_b
    {
        dim3 g((Hh + 63) / 64, (Bb + 63) / 64);
        sgemm_bias_kernel<<<g, 256>>>(p_ht, fc1_w, fc1_b, p_q1, Bb, Hh, Hh);
    }
    // 10. q2 = seq_h @ fc2_w.T + fc2_b
    {
        dim3 g((Hh + 63) / 64, (BN + 63) / 64);
        sgemm_bias_kernel<<<g, 256>>>(p_seqh, fc2_w, fc2_b, p_q2, Bb * Ss, Hh, Hh);
    }
    // 11. attention -> a
    attn_kernel<<<Bb, 128>>>(p_q1, p_q2, fc3_w, p_seqh, mask, p_avec);
    // 12. out = a @ emb[1:].T   (M=1024, N=99999, K=128)
    {
        int Nout = Vv - 1;
        dim3 g((Nout + 63) / 64, (Bb + 63) / 64);
        sgemm_bias_kernel<<<g, 256>>>(p_avec, emb + Hh, nullptr, out,
                                      Bb, Nout, Hh);
    }
    (void)in_sizes; (void)n_in; (void)out_size;
}

// round 4
// speedup vs baseline: 1.4874x; 1.4874x over previous
#include <cuda_runtime.h>
#include <cuda_bf16.h>
#include <cstdint>

// SR-GNN forward. Shapes fixed: B=1024, N=50, S=50, H=128, V=100000
#define Bb 1024
#define Nn 50
#define Ss 50
#define Hh 128
#define Vv 100000

// ---------------- scratch ---------------------------------------------------
__device__ float g_h     [Bb * Nn * Hh];
__device__ float g_hin   [Bb * Nn * Hh];
__device__ float g_hout  [Bb * Nn * Hh];
__device__ float g_inputs[Bb * Nn * 2 * Hh];
__device__ float g_gi    [Bb * Nn * 3 * Hh];
__device__ float g_gh    [Bb * Nn * 3 * Hh];
__device__ float g_newh  [Bb * Nn * Hh];
__device__ float g_seqh  [Bb * Ss * Hh];
__device__ float g_ht    [Bb * Hh];
__device__ float g_q1    [Bb * Hh];
__device__ float g_q2    [Bb * Ss * Hh];
__device__ float g_avec  [Bb * Hh];

// ---------------- tf32 helpers ----------------------------------------------
__device__ __forceinline__ uint32_t f2tf32(float x) {
    uint32_t r;
    asm("cvt.rna.tf32.f32 %0, %1;" : "=r"(r) : "f"(x));
    return r;
}
__device__ __forceinline__ void mma_tf32(float* c, const uint32_t* a,
                                         const uint32_t* b) {
    asm volatile(
        "mma.sync.aligned.m16n8k8.row.col.f32.tf32.tf32.f32 "
        "{%0,%1,%2,%3}, {%4,%5,%6,%7}, {%8,%9}, {%0,%1,%2,%3};"
        : "+f"(c[0]), "+f"(c[1]), "+f"(c[2]), "+f"(c[3])
        : "r"(a[0]), "r"(a[1]), "r"(a[2]), "r"(a[3]), "r"(b[0]), "r"(b[1]));
}

// ---------------- HMMA tf32 GEMM: C[M,N] = A[M,K] @ W[N,K]^T (+bias) --------
// 128x128 tile, BK=32, 256 threads (8 warps = 2M x 4N, warp tile 64x32).
// Requires: M % 128 == 0, K % 32 == 0. N arbitrary (guarded, scalar stores).
__global__ void __launch_bounds__(256)
gemm_mma_kernel(const float* __restrict__ A, const float* __restrict__ W,
                const float* __restrict__ bias, float* __restrict__ C,
                int M, int N, int K) {
    __shared__ uint32_t sA[128][36];     // stride 36 -> conflict-free frags
    __shared__ uint32_t sB[128][36];

    const int tid  = threadIdx.x;
    const int warp = tid >> 5, lane = tid & 31;
    const int g  = lane >> 2;            // group id 0..7
    const int tg = lane & 3;             // thread-in-group 0..3
    const int wm = (warp & 1) * 64;      // warp M offset
    const int wn = (warp >> 1) * 32;     // warp N offset
    const int m0 = blockIdx.y * 128;
    const int n0 = blockIdx.x * 128;

    float acc[4][4][4];
#pragma unroll
    for (int mt = 0; mt < 4; mt++)
#pragma unroll
        for (int nt = 0; nt < 4; nt++)
#pragma unroll
            for (int i = 0; i < 4; i++) acc[mt][nt][i] = 0.f;

    for (int kt = 0; kt < K; kt += 32) {
        // stage both tiles: 128 rows x 8 float4 each
#pragma unroll
        for (int i = tid; i < 1024; i += 256) {
            int r = i >> 3, q = i & 7;
            float4 v = make_float4(0.f, 0.f, 0.f, 0.f);
            int gr = m0 + r;
            if (gr < M) v = *(const float4*)(A + (size_t)gr * K + kt + q * 4);
            uint32_t* da = &sA[r][q * 4];
            da[0] = f2tf32(v.x); da[1] = f2tf32(v.y);
            da[2] = f2tf32(v.z); da[3] = f2tf32(v.w);

            float4 w4 = make_float4(0.f, 0.f, 0.f, 0.f);
            int gw = n0 + r;
            if (gw < N) w4 = *(const float4*)(W + (size_t)gw * K + kt + q * 4);
            uint32_t* db = &sB[r][q * 4];
            db[0] = f2tf32(w4.x); db[1] = f2tf32(w4.y);
            db[2] = f2tf32(w4.z); db[3] = f2tf32(w4.w);
        }
        __syncthreads();

#pragma unroll
        for (int ks = 0; ks < 4; ks++) {
            const int kk = ks * 8;
            uint32_t af[4][4], bf[4][2];
#pragma unroll
            for (int mt = 0; mt < 4; mt++) {
                int rb = wm + mt * 16;
                af[mt][0] = sA[rb + g][kk + tg];
                af[mt][1] = sA[rb + g + 8][kk + tg];
                af[mt][2] = sA[rb + g][kk + tg + 4];
                af[mt][3] = sA[rb + g + 8][kk + tg + 4];
            }
#pragma unroll
            for (int nt = 0; nt < 4; nt++) {
                int nb = wn + nt * 8;
                bf[nt][0] = sB[nb + g][kk + tg];
                bf[nt][1] = sB[nb + g][kk + tg + 4];
            }
#pragma unroll
            for (int mt = 0; mt < 4; mt++)
#pragma unroll
                for (int nt = 0; nt < 4; nt++)
                    mma_tf32(acc[mt][nt], af[mt], bf[nt]);
        }
        __syncthreads();
    }

    // epilogue — scalar stores (N may be odd; C rows then not float2-aligned)
#pragma unroll
    for (int mt = 0; mt < 4; mt++) {
        int row = m0 + wm + mt * 16 + g;
#pragma unroll
        for (int nt = 0; nt < 4; nt++) {
            int col = n0 + wn + nt * 8 + tg * 2;
            const float* c0 = &acc[mt][nt][0];
            if (col < N) {
                float b0 = bias ? __ldg(bias + col) : 0.f;
                C[(size_t)row * N + col]       = c0[0] + b0;
                C[(size_t)(row + 8) * N + col] = c0[2] + b0;
            }
            if (col + 1 < N) {
                float b1 = bias ? __ldg(bias + col + 1) : 0.f;
                C[(size_t)row * N + col + 1]       = c0[1] + b1;
                C[(size_t)(row + 8) * N + col + 1] = c0[3] + b1;
            }
        }
    }
}

// ---------------- h = emb[items] --------------------------------------------
__global__ void gather_kernel(const int* __restrict__ items,
                              const float* __restrict__ emb,
                              float* __restrict__ h, int total4) {
    int i = blockIdx.x * blockDim.x + threadIdx.x;
    if (i >= total4) return;
    int bn = i >> 5, q = i & 31;
    int it = items[bn];
    ((float4*)h)[i] = ((const float4*)emb)[(size_t)it * 32 + q];
}

// ---------------- batched adjacency matmul ----------------------------------
__global__ void amm_kernel(const float* __restrict__ Amat,
                           const float* __restrict__ hin,
                           const float* __restrict__ hout,
                           const float* __restrict__ b_iah,
                           const float* __restrict__ b_oah,
                           float* __restrict__ inputs) {
    int b = blockIdx.x;
    int tid = threadIdx.x;                 // 256 threads
    __shared__ float sA[Nn * Nn];
    __shared__ __align__(16) float sH[Nn * Hh];
    const float* Ab = Amat + (size_t)b * Nn * 2 * Nn;

#pragma unroll
    for (int pass = 0; pass < 2; pass++) {
        const float* hsrc = pass ? hout : hin;
        const float* bias = pass ? b_oah : b_iah;
        int acol = pass ? Nn : 0;
        for (int i = tid; i < Nn * Nn; i += 256)
            sA[i] = Ab[(i / Nn) * (2 * Nn) + acol + (i % Nn)];
        for (int i = tid; i < Nn * (Hh / 4); i += 256)
            ((float4*)sH)[i] = ((const float4*)(hsrc + (size_t)b * Nn * Hh))[i];
        __syncthreads();
        for (int o = tid; o < Nn * 32; o += 256) {
            int n = o >> 5, q = o & 31;
            float4 acc = *(const float4*)(bias + q * 4);
#pragma unroll 10
            for (int k = 0; k < Nn; k++) {
                float a = sA[n * Nn + k];
                float4 hv = *(const float4*)&sH[k * Hh + q * 4];
                acc.x += a * hv.x; acc.y += a * hv.y;
                acc.z += a * hv.z; acc.w += a * hv.w;
            }
            *(float4*)(inputs + ((size_t)b * Nn + n) * (2 * Hh) + pass * Hh + q * 4) = acc;
        }
        __syncthreads();
    }
}

// ---------------- GRU gate math ---------------------------------------------
__global__ void gru_kernel(const float* __restrict__ gi,
                           const float* __restrict__ gh,
                           const float* __restrict__ h,
                           float* __restrict__ newh, int total) {
    int i = blockIdx.x * blockDim.x + threadIdx.x;
    if (i >= total) return;
    int bn = i / Hh, hh = i - bn * Hh;
    size_t base = (size_t)bn * 3 * Hh;
    float i_r = gi[base + hh];
    float i_i = gi[base + Hh + hh];
    float i_n = gi[base + 2 * Hh + hh];
    float h_r = gh[base + hh];
    float h_i = gh[base + Hh + hh];
    float h_n = gh[base + 2 * Hh + hh];
    float r = 1.f / (1.f + expf(-(i_r + h_r)));
    float z = 1.f / (1.f + expf(-(i_i + h_i)));
    float ng = tanhf(i_n + r * h_n);
    newh[i] = ng + z * (h[i] - ng);
}

// ---------------- alias gather + ht -----------------------------------------
__global__ void seq_kernel(const int* __restrict__ alias,
                           const int* __restrict__ mask,
                           const float* __restrict__ newh,
                           float* __restrict__ seqh,
                           float* __restrict__ ht) {
    int b = blockIdx.x;
    int tid = threadIdx.x;                 // 256
    __shared__ int sal[Ss];
    __shared__ int slast;
    if (tid < Ss) sal[tid] = alias[b * Ss + tid];
    if (tid == 0) {
        int c = 0;
        for (int s = 0; s < Ss; s++) c += mask[b * Ss + s];
        slast = c - 1;
    }
    __syncthreads();
    const float4* src = (const float4*)newh + (size_t)b * Nn * (Hh / 4);
    float4* dst = (float4*)seqh + (size_t)b * Ss * (Hh / 4);
    for (int i = tid; i < Ss * (Hh / 4); i += 256) {
        int s = i >> 5, q = i & 31;
        dst[i] = src[sal[s] * 32 + q];
    }
    if (tid < 32) {
        const float4* hrow = (const float4*)newh + ((size_t)b * Nn + sal[slast]) * (Hh / 4);
        ((float4*)ht)[(size_t)b * (Hh / 4) + tid] = hrow[tid];
    }
}

// ---------------- attention readout -----------------------------------------
__global__ void attn_kernel(const float* __restrict__ q1,
                            const float* __restrict__ q2,
                            const float* __restrict__ fc3_w,
                            const float* __restrict__ seqh,
                            const int* __restrict__ mask,
                            float* __restrict__ avec) {
    int b = blockIdx.x;
    int tid = threadIdx.x;                 // 128
    int warp = tid >> 5, lane = tid & 31;
    __shared__ float salpha[Ss];
    for (int s = warp; s < Ss; s += 4) {
        float part = 0.f;
        for (int hh = lane; hh < Hh; hh += 32) {
            float v = q1[(size_t)b * Hh + hh] + q2[((size_t)b * Ss + s) * Hh + hh];
            part += fc3_w[hh] / (1.f + expf(-v));
        }
#pragma unroll
        for (int off = 16; off; off >>= 1)
            part += __shfl_down_sync(0xffffffffu, part, off);
        if (lane == 0) salpha[s] = part;
    }
    __syncthreads();
    int hh = tid;
    float acc = 0.f;
    for (int s = 0; s < Ss; s++) {
        float m = (float)mask[b * Ss + s];
        acc += salpha[s] * seqh[((size_t)b * Ss + s) * Hh + hh] * m;
    }
    avec[(size_t)b * Hh + hh] = acc;
}

// ---------------- launch -----------------------------------------------------
extern "C" void kernel_launch(void* const* d_in, const int* in_sizes, int n_in,
                              void* d_out, int out_size) {
    const int*   alias_inputs = (const int*)  d_in[0];
    const float* A            = (const float*)d_in[1];
    const int*   items        = (const int*)  d_in[2];
    const int*   mask         = (const int*)  d_in[3];
    const float* emb          = (const float*)d_in[4];
    const float* ein_w        = (const float*)d_in[5];
    const float* ein_b        = (const float*)d_in[6];
    const float* eou_w        = (const float*)d_in[7];
    const float* eou_b        = (const float*)d_in[8];
    const float* w_ih         = (const float*)d_in[9];
    const float* w_hh         = (const float*)d_in[10];
    const float* b_ih         = (const float*)d_in[11];
    const float* b_hh         = (const float*)d_in[12];
    const float* b_iah        = (const float*)d_in[13];
    const float* b_oah        = (const float*)d_in[14];
    const float* fc1_w        = (const float*)d_in[15];
    const float* fc1_b        = (const float*)d_in[16];
    const float* fc2_w        = (const float*)d_in[17];
    const float* fc2_b        = (const float*)d_in[18];
    const float* fc3_w        = (const float*)d_in[19];
    float* out = (float*)d_out;

    float *p_h, *p_hin, *p_hout, *p_inputs, *p_gi, *p_gh, *p_newh;
    float *p_seqh, *p_ht, *p_q1, *p_q2, *p_avec;
    cudaGetSymbolAddress((void**)&p_h,      g_h);
    cudaGetSymbolAddress((void**)&p_hin,    g_hin);
    cudaGetSymbolAddress((void**)&p_hout,   g_hout);
    cudaGetSymbolAddress((void**)&p_inputs, g_inputs);
    cudaGetSymbolAddress((void**)&p_gi,     g_gi);
    cudaGetSymbolAddress((void**)&p_gh,     g_gh);
    cudaGetSymbolAddress((void**)&p_newh,   g_newh);
    cudaGetSymbolAddress((void**)&p_seqh,   g_seqh);
    cudaGetSymbolAddress((void**)&p_ht,     g_ht);
    cudaGetSymbolAddress((void**)&p_q1,     g_q1);
    cudaGetSymbolAddress((void**)&p_q2,     g_q2);
    cudaGetSymbolAddress((void**)&p_avec,   g_avec);

    const int BN = Bb * Nn;                // 51200 = 400 * 128

    // 1. gather
    {
        int total4 = BN * (Hh / 4);
        gather_kernel<<<(total4 + 255) / 256, 256>>>(items, emb, p_h, total4);
    }
    // 2,3. hin / hout  (M=51200, N=128, K=128)
    gemm_mma_kernel<<<dim3(1, BN / 128), 256>>>(p_h, ein_w, ein_b, p_hin, BN, Hh, Hh);
    gemm_mma_kernel<<<dim3(1, BN / 128), 256>>>(p_h, eou_w, eou_b, p_hout, BN, Hh, Hh);
    // 4. gh  (N=384, K=128)
    gemm_mma_kernel<<<dim3(3, BN / 128), 256>>>(p_h, w_hh, b_hh, p_gh, BN, 3 * Hh, Hh);
    // 5. adjacency matmuls
    amm_kernel<<<Bb, 256>>>(A, p_hin, p_hout, b_iah, b_oah, p_inputs);
    // 6. gi  (N=384, K=256)
    gemm_mma_kernel<<<dim3(3, BN / 128), 256>>>(p_inputs, w_ih, b_ih, p_gi,
                                                BN, 3 * Hh, 2 * Hh);
    // 7. GRU
    {
        int total = BN * Hh;
        gru_kernel<<<(total + 255) / 256, 256>>>(p_gi, p_gh, p_h, p_newh, total);
    }
    // 8. seq gather + ht
    seq_kernel<<<Bb, 256>>>(alias_inputs, mask, p_newh, p_seqh, p_ht);
    // 9. q1 (M=1024, N=128, K=128)
    gemm_mma_kernel<<<dim3(1, Bb / 128), 256>>>(p_ht, fc1_w, fc1_b, p_q1, Bb, Hh, Hh);
    // 10. q2 (M=51200, N=128, K=128)
    gemm_mma_kernel<<<dim3(1, BN / 128), 256>>>(p_seqh, fc2_w, fc2_b, p_q2,
                                                Bb * Ss, Hh, Hh);
    // 11. attention
    attn_kernel<<<Bb, 128>>>(p_q1, p_q2, fc3_w, p_seqh, mask, p_avec);
    // 12. out = a @ emb[1:].T  (M=1024, N=99999, K=128)
    {
        int Nout = Vv - 1;
        gemm_mma_kernel<<<dim3((Nout + 127) / 128, Bb / 128), 256>>>(
            p_avec, emb + Hh, nullptr, out, Bb, Nout, Hh);
    }
    (void)in_sizes; (void)n_in; (void)out_size;
}

// round 6
// speedup vs baseline: 2.3023x; 1.5478x over previous
#include <cuda_runtime.h>
#include <cuda_bf16.h>
#include <cstdint>

// SR-GNN forward. Shapes fixed: B=1024, N=50, S=50, H=128, V=100000
#define Bb 1024
#define Nn 50
#define Ss 50
#define Hh 128
#define Vv 100000

// ---------------- scratch ---------------------------------------------------
__device__ float g_h     [Bb * Nn * Hh];
__device__ float g_hin   [Bb * Nn * Hh];
__device__ float g_hout  [Bb * Nn * Hh];
__device__ float g_inputs[Bb * Nn * 2 * Hh];
__device__ float g_gi    [Bb * Nn * 3 * Hh];
__device__ float g_gh    [Bb * Nn * 3 * Hh];
__device__ float g_newh  [Bb * Nn * Hh];
__device__ float g_seqh  [Bb * Ss * Hh];
__device__ float g_ht    [Bb * Hh];
__device__ float g_q1    [Bb * Hh];
__device__ float g_q2    [Bb * Ss * Hh];
__device__ float g_avec  [Bb * Hh];
__device__ float g_embr  [Vv * Hh];        // tf32-rounded emb
__device__ float g_wr    [212992];         // tf32-rounded weights (packed)

// packed weight offsets
#define WR_EIN 0
#define WR_EOU 16384
#define WR_WHH 32768
#define WR_WIH 81920
#define WR_FC1 180224
#define WR_FC2 196608

// ---------------- tf32 helpers ----------------------------------------------
__device__ __forceinline__ uint32_t f2tf32(float x) {
    uint32_t r;
    asm("cvt.rna.tf32.f32 %0, %1;" : "=r"(r) : "f"(x));
    return r;
}
__device__ __forceinline__ float roundtf(float x) {
    return __uint_as_float(f2tf32(x));
}
__device__ __forceinline__ void mma_tf32(float* c, const uint32_t* a,
                                         const uint32_t* b) {
    asm volatile(
        "mma.sync.aligned.m16n8k8.row.col.f32.tf32.tf32.f32 "
        "{%0,%1,%2,%3}, {%4,%5,%6,%7}, {%8,%9}, {%0,%1,%2,%3};"
        : "+f"(c[0]), "+f"(c[1]), "+f"(c[2]), "+f"(c[3])
        : "r"(a[0]), "r"(a[1]), "r"(a[2]), "r"(a[3]), "r"(b[0]), "r"(b[1]));
}
__device__ __forceinline__ void cp16(uint32_t dst, const void* src, bool pred) {
    int sz = pred ? 16 : 0;
    asm volatile("cp.async.cg.shared.global [%0], [%1], 16, %2;\n"
                 :: "r"(dst), "l"(src), "r"(sz));
}

// ---------------- tf32 round-copy kernel ------------------------------------
__global__ void round_kernel(const float* __restrict__ src,
                             float* __restrict__ dst, int n4) {
    int i = blockIdx.x * blockDim.x + threadIdx.x;
    if (i >= n4) return;
    float4 v = ((const float4*)src)[i];
    ((float4*)dst)[i] = make_float4(roundtf(v.x), roundtf(v.y),
                                    roundtf(v.z), roundtf(v.w));
}

// ---------------- HMMA tf32 GEMM v2 -----------------------------------------
// C[M,N] = A[M,K] @ W[N,K]^T (+bias). Inputs MUST be pre-rounded to tf32.
// CTA 128x128, 128 threads = 4 warps (2x2 of 64x64 warp tiles), BK=32,
// double-buffered cp.async. Requires M%128==0, K%32==0. N guarded.
// smem per buffer: A 128x36 u32 (18432B) + B same. 2 buffers -> 73728B.
#define GBUF 18432
__global__ void __launch_bounds__(128, 2)
gemm2_kernel(const float* __restrict__ A, const float* __restrict__ W,
             const float* __restrict__ bias, float* __restrict__ C,
             int M, int N, int K) {
    extern __shared__ char dsm[];
    const uint32_t sbase = (uint32_t)__cvta_generic_to_shared(dsm);
    const int tid  = threadIdx.x;
    const int warp = tid >> 5, lane = tid & 31;
    const int g  = lane >> 2;
    const int tg = lane & 3;
    const int wm = (warp & 1) * 64;
    const int wn = (warp >> 1) * 64;
    const int m0 = blockIdx.y * 128;
    const int n0 = blockIdx.x * 128;

    float acc[4][8][4];
#pragma unroll
    for (int mt = 0; mt < 4; mt++)
#pragma unroll
        for (int nt = 0; nt < 8; nt++)
#pragma unroll
            for (int i = 0; i < 4; i++) acc[mt][nt][i] = 0.f;

    const int nch = K >> 5;

    // ---- staging lambda: chunk c -> buf s ----
    auto stage = [&](int c, int s) {
        const int kt = c * 32;
        uint32_t aB = sbase + s * GBUF;
        uint32_t bB = sbase + 2 * GBUF + s * GBUF;
#pragma unroll
        for (int i = 0; i < 4; i++) {
            int idx = tid + i * 128;       // 512 chunks of 32B? no: 16B x 1024
            // handle 1024 chunks in 8 slices of 128: do two per i
#pragma unroll
            for (int h = 0; h < 2; h++) {
                int id2 = idx + h * 512;
                int row = id2 >> 3, q = id2 & 7;
                bool pa = (m0 + row) < M;
                const float* sa = pa ? (A + (size_t)(m0 + row) * K + kt + q * 4) : A;
                cp16(aB + row * 144 + q * 16, sa, pa);
                bool pb = (n0 + row) < N;
                const float* sb = pb ? (W + (size_t)(n0 + row) * K + kt + q * 4) : W;
                cp16(bB + row * 144 + q * 16, sb, pb);
            }
        }
        asm volatile("cp.async.commit_group;\n" ::: "memory");
    };

    stage(0, 0);
    for (int c = 0; c < nch; c++) {
        if (c + 1 < nch) {
            stage(c + 1, (c + 1) & 1);
            asm volatile("cp.async.wait_group 1;" ::: "memory");
        } else {
            asm volatile("cp.async.wait_group 0;" ::: "memory");
        }
        __syncthreads();

        const uint32_t (*sA)[36] =
            (const uint32_t (*)[36])(dsm + (c & 1) * GBUF);
        const uint32_t (*sB)[36] =
            (const uint32_t (*)[36])(dsm + 2 * GBUF + (c & 1) * GBUF);

#pragma unroll
        for (int ks = 0; ks < 4; ks++) {
            const int kk = ks * 8;
            uint32_t af[4][4], bf[8][2];
#pragma unroll
            for (int mt = 0; mt < 4; mt++) {
                int rb = wm + mt * 16;
                af[mt][0] = sA[rb + g][kk + tg];
                af[mt][1] = sA[rb + g + 8][kk + tg];
                af[mt][2] = sA[rb + g][kk + tg + 4];
                af[mt][3] = sA[rb + g + 8][kk + tg + 4];
            }
#pragma unroll
            for (int nt = 0; nt < 8; nt++) {
                int nb = wn + nt * 8;
                bf[nt][0] = sB[nb + g][kk + tg];
                bf[nt][1] = sB[nb + g][kk + tg + 4];
            }
#pragma unroll
            for (int mt = 0; mt < 4; mt++)
#pragma unroll
                for (int nt = 0; nt < 8; nt++)
                    mma_tf32(acc[mt][nt], af[mt], bf[nt]);
        }
        __syncthreads();
    }

    // epilogue — scalar stores (N may be odd)
#pragma unroll
    for (int mt = 0; mt < 4; mt++) {
        int row = m0 + wm + mt * 16 + g;
#pragma unroll
        for (int nt = 0; nt < 8; nt++) {
            int col = n0 + wn + nt * 8 + tg * 2;
            const float* c0 = &acc[mt][nt][0];
            if (col < N) {
                float b0 = bias ? __ldg(bias + col) : 0.f;
                C[(size_t)row * N + col]       = c0[0] + b0;
                C[(size_t)(row + 8) * N + col] = c0[2] + b0;
            }
            if (col + 1 < N) {
                float b1 = bias ? __ldg(bias + col + 1) : 0.f;
                C[(size_t)row * N + col + 1]       = c0[1] + b1;
                C[(size_t)(row + 8) * N + col + 1] = c0[3] + b1;
            }
        }
    }
}

// ---------------- h = emb[items] (from rounded emb) --------------------------
__global__ void gather_kernel(const int* __restrict__ items,
                              const float* __restrict__ embr,
                              float* __restrict__ h, int total4) {
    int i = blockIdx.x * blockDim.x + threadIdx.x;
    if (i >= total4) return;
    int bn = i >> 5, q = i & 31;
    int it = items[bn];
    ((float4*)h)[i] = ((const float4*)embr)[(size_t)it * 32 + q];
}

// ---------------- batched adjacency matmul (rounded output) ------------------
__global__ void amm_kernel(const float* __restrict__ Amat,
                           const float* __restrict__ hin,
                           const float* __restrict__ hout,
                           const float* __restrict__ b_iah,
                           const float* __restrict__ b_oah,
                           float* __restrict__ inputs) {
    int b = blockIdx.x;
    int tid = threadIdx.x;                 // 256 threads
    __shared__ float sA[Nn * Nn];
    __shared__ __align__(16) float sH[Nn * Hh];
    const float* Ab = Amat + (size_t)b * Nn * 2 * Nn;

#pragma unroll
    for (int pass = 0; pass < 2; pass++) {
        const float* hsrc = pass ? hout : hin;
        const float* bias = pass ? b_oah : b_iah;
        int acol = pass ? Nn : 0;
        for (int i = tid; i < Nn * Nn; i += 256)
            sA[i] = Ab[(i / Nn) * (2 * Nn) + acol + (i % Nn)];
        for (int i = tid; i < Nn * (Hh / 4); i += 256)
            ((float4*)sH)[i] = ((const float4*)(hsrc + (size_t)b * Nn * Hh))[i];
        __syncthreads();
        for (int o = tid; o < Nn * 32; o += 256) {
            int n = o >> 5, q = o & 31;
            float4 acc = *(const float4*)(bias + q * 4);
#pragma unroll 10
            for (int k = 0; k < Nn; k++) {
                float a = sA[n * Nn + k];
                float4 hv = *(const float4*)&sH[k * Hh + q * 4];
                acc.x += a * hv.x; acc.y += a * hv.y;
                acc.z += a * hv.z; acc.w += a * hv.w;
            }
            acc.x = roundtf(acc.x); acc.y = roundtf(acc.y);
            acc.z = roundtf(acc.z); acc.w = roundtf(acc.w);
            *(float4*)(inputs + ((size_t)b * Nn + n) * (2 * Hh) + pass * Hh + q * 4) = acc;
        }
        __syncthreads();
    }
}

// ---------------- GRU gate math (rounded output) ------------------------------
__global__ void gru_kernel(const float* __restrict__ gi,
                           const float* __restrict__ gh,
                           const float* __restrict__ h,
                           float* __restrict__ newh, int total) {
    int i = blockIdx.x * blockDim.x + threadIdx.x;
    if (i >= total) return;
    int bn = i / Hh, hh = i - bn * Hh;
    size_t base = (size_t)bn * 3 * Hh;
    float i_r = gi[base + hh];
    float i_i = gi[base + Hh + hh];
    float i_n = gi[base + 2 * Hh + hh];
    float h_r = gh[base + hh];
    float h_i = gh[base + Hh + hh];
    float h_n = gh[base + 2 * Hh + hh];
    float r = 1.f / (1.f + expf(-(i_r + h_r)));
    float z = 1.f / (1.f + expf(-(i_i + h_i)));
    float ng = tanhf(i_n + r * h_n);
    newh[i] = roundtf(ng + z * (h[i] - ng));
}

// ---------------- alias gather + ht ------------------------------------------
__global__ void seq_kernel(const int* __restrict__ alias,
                           const int* __restrict__ mask,
                           const float* __restrict__ newh,
                           float* __restrict__ seqh,
                           float* __restrict__ ht) {
    int b = blockIdx.x;
    int tid = threadIdx.x;                 // 256
    __shared__ int sal[Ss];
    __shared__ int slast;
    if (tid < Ss) sal[tid] = alias[b * Ss + tid];
    if (tid == 0) {
        int c = 0;
        for (int s = 0; s < Ss; s++) c += mask[b * Ss + s];
        slast = c - 1;
    }
    __syncthreads();
    const float4* src = (const float4*)newh + (size_t)b * Nn * (Hh / 4);
    float4* dst = (float4*)seqh + (size_t)b * Ss * (Hh / 4);
    for (int i = tid; i < Ss * (Hh / 4); i += 256) {
        int s = i >> 5, q = i & 31;
        dst[i] = src[sal[s] * 32 + q];
    }
    if (tid < 32) {
        const float4* hrow = (const float4*)newh + ((size_t)b * Nn + sal[slast]) * (Hh / 4);
        ((float4*)ht)[(size_t)b * (Hh / 4) + tid] = hrow[tid];
    }
}

// ---------------- attention readout (rounded output) --------------------------
__global__ void attn_kernel(const float* __restrict__ q1,
                            const float* __restrict__ q2,
                            const float* __restrict__ fc3_w,
                            const float* __restrict__ seqh,
                            const int* __restrict__ mask,
                            float* __restrict__ avec) {
    int b = blockIdx.x;
    int tid = threadIdx.x;                 // 128
    int warp = tid >> 5, lane = tid & 31;
    __shared__ float salpha[Ss];
    for (int s = warp; s < Ss; s += 4) {
        float part = 0.f;
        for (int hh = lane; hh < Hh; hh += 32) {
            float v = q1[(size_t)b * Hh + hh] + q2[((size_t)b * Ss + s) * Hh + hh];
            part += fc3_w[hh] / (1.f + expf(-v));
        }
#pragma unroll
        for (int off = 16; off; off >>= 1)
            part += __shfl_down_sync(0xffffffffu, part, off);
        if (lane == 0) salpha[s] = part;
    }
    __syncthreads();
    int hh = tid;
    float acc = 0.f;
    for (int s = 0; s < Ss; s++) {
        float m = (float)mask[b * Ss + s];
        acc += salpha[s] * seqh[((size_t)b * Ss + s) * Hh + hh] * m;
    }
    avec[(size_t)b * Hh + hh] = roundtf(acc);
}

// ---------------- launch -----------------------------------------------------
extern "C" void kernel_launch(void* const* d_in, const int* in_sizes, int n_in,
                              void* d_out, int out_size) {
    const int*   alias_inputs = (const int*)  d_in[0];
    const float* A            = (const float*)d_in[1];
    const int*   items        = (const int*)  d_in[2];
    const int*   mask         = (const int*)  d_in[3];
    const float* emb          = (const float*)d_in[4];
    const float* ein_w        = (const float*)d_in[5];
    const float* ein_b        = (const float*)d_in[6];
    const float* eou_w        = (const float*)d_in[7];
    const float* eou_b        = (const float*)d_in[8];
    const float* w_ih         = (const float*)d_in[9];
    const float* w_hh         = (const float*)d_in[10];
    const float* b_ih         = (const float*)d_in[11];
    const float* b_hh         = (const float*)d_in[12];
    const float* b_iah        = (const float*)d_in[13];
    const float* b_oah        = (const float*)d_in[14];
    const float* fc1_w        = (const float*)d_in[15];
    const float* fc1_b        = (const float*)d_in[16];
    const float* fc2_w        = (const float*)d_in[17];
    const float* fc2_b        = (const float*)d_in[18];
    const float* fc3_w        = (const float*)d_in[19];
    float* out = (float*)d_out;

    static int smem_set = 0;
    if (!smem_set) {
        cudaFuncSetAttribute(gemm2_kernel,
                             cudaFuncAttributeMaxDynamicSharedMemorySize,
                             4 * GBUF);
        smem_set = 1;
    }

    float *p_h, *p_hin, *p_hout, *p_inputs, *p_gi, *p_gh, *p_newh;
    float *p_seqh, *p_ht, *p_q1, *p_q2, *p_avec, *p_embr, *p_wr;
    cudaGetSymbolAddress((void**)&p_h,      g_h);
    cudaGetSymbolAddress((void**)&p_hin,    g_hin);
    cudaGetSymbolAddress((void**)&p_hout,   g_hout);
    cudaGetSymbolAddress((void**)&p_inputs, g_inputs);
    cudaGetSymbolAddress((void**)&p_gi,     g_gi);
    cudaGetSymbolAddress((void**)&p_gh,     g_gh);
    cudaGetSymbolAddress((void**)&p_newh,   g_newh);
    cudaGetSymbolAddress((void**)&p_seqh,   g_seqh);
    cudaGetSymbolAddress((void**)&p_ht,     g_ht);
    cudaGetSymbolAddress((void**)&p_q1,     g_q1);
    cudaGetSymbolAddress((void**)&p_q2,     g_q2);
    cudaGetSymbolAddress((void**)&p_avec,   g_avec);
    cudaGetSymbolAddress((void**)&p_embr,   g_embr);
    cudaGetSymbolAddress((void**)&p_wr,     g_wr);

    const int BN = Bb * Nn;                // 51200 = 400 * 128
    const int SM = 4 * GBUF;               // dynamic smem for gemm2

    // 0. pre-round emb + weights to tf32
    {
        int n4 = Vv * Hh / 4;
        round_kernel<<<(n4 + 255) / 256, 256>>>(emb, p_embr, n4);
        round_kernel<<<(16384 / 4 + 255) / 256, 256>>>(ein_w, p_wr + WR_EIN, 16384 / 4);
        round_kernel<<<(16384 / 4 + 255) / 256, 256>>>(eou_w, p_wr + WR_EOU, 16384 / 4);
        round_kernel<<<(49152 / 4 + 255) / 256, 256>>>(w_hh,  p_wr + WR_WHH, 49152 / 4);
        round_kernel<<<(98304 / 4 + 255) / 256, 256>>>(w_ih,  p_wr + WR_WIH, 98304 / 4);
        round_kernel<<<(16384 / 4 + 255) / 256, 256>>>(fc1_w, p_wr + WR_FC1, 16384 / 4);
        round_kernel<<<(16384 / 4 + 255) / 256, 256>>>(fc2_w, p_wr + WR_FC2, 16384 / 4);
    }
    // 1. gather (rounded)
    {
        int total4 = BN * (Hh / 4);
        gather_kernel<<<(total4 + 255) / 256, 256>>>(items, p_embr, p_h, total4);
    }
    // 2,3. hin / hout  (M=51200, N=128, K=128)
    gemm2_kernel<<<dim3(1, BN / 128), 128, SM>>>(p_h, p_wr + WR_EIN, ein_b, p_hin, BN, Hh, Hh);
    gemm2_kernel<<<dim3(1, BN / 128), 128, SM>>>(p_h, p_wr + WR_EOU, eou_b, p_hout, BN, Hh, Hh);
    // 4. gh  (N=384, K=128)
    gemm2_kernel<<<dim3(3, BN / 128), 128, SM>>>(p_h, p_wr + WR_WHH, b_hh, p_gh, BN, 3 * Hh, Hh);
    // 5. adjacency matmuls
    amm_kernel<<<Bb, 256>>>(A, p_hin, p_hout, b_iah, b_oah, p_inputs);
    // 6. gi  (N=384, K=256)
    gemm2_kernel<<<dim3(3, BN / 128), 128, SM>>>(p_inputs, p_wr + WR_WIH, b_ih, p_gi,
                                                 BN, 3 * Hh, 2 * Hh);
    // 7. GRU
    {
        int total = BN * Hh;
        gru_kernel<<<(total + 255) / 256, 256>>>(p_gi, p_gh, p_h, p_newh, total);
    }
    // 8. seq gather + ht
    seq_kernel<<<Bb, 256>>>(alias_inputs, mask, p_newh, p_seqh, p_ht);
    // 9. q1 (M=1024, N=128, K=128)
    gemm2_kernel<<<dim3(1, Bb / 128), 128, SM>>>(p_ht, p_wr + WR_FC1, fc1_b, p_q1, Bb, Hh, Hh);
    // 10. q2 (M=51200, N=128, K=128)
    gemm2_kernel<<<dim3(1, BN / 128), 128, SM>>>(p_seqh, p_wr + WR_FC2, fc2_b, p_q2,
                                                 Bb * Ss, Hh, Hh);
    // 11. attention
    attn_kernel<<<Bb, 128>>>(p_q1, p_q2, fc3_w, p_seqh, mask, p_avec);
    // 12. out = a @ emb[1:].T  (M=1024, N=99999, K=128)
    {
        int Nout = Vv - 1;
        gemm2_kernel<<<dim3((Nout + 127) / 128, Bb / 128), 128, SM>>>(
            p_avec, p_embr + Hh, nullptr, out, Bb, Nout, Hh);
    }
    (void)in_sizes; (void)n_in; (void)out_size;
}

// round 7
// speedup vs baseline: 2.5812x; 1.1211x over previous
#include <cuda_runtime.h>
#include <cuda_bf16.h>
#include <cstdint>

// SR-GNN forward. Shapes fixed: B=1024, N=50, S=50, H=128, V=100000
#define Bb 1024
#define Nn 50
#define Ss 50
#define Hh 128
#define Vv 100000

// ---------------- scratch ---------------------------------------------------
__device__ float g_h     [Bb * Nn * Hh];
__device__ float g_cat   [Bb * Nn * 640];     // [hin(128) | hout(128) | gh(384)]
__device__ float g_inputs[Bb * Nn * 2 * Hh];
__device__ float g_gi    [Bb * Nn * 3 * Hh];
__device__ float g_newh  [Bb * Nn * Hh];
__device__ float g_seqh  [Bb * Ss * Hh];
__device__ float g_ht    [Bb * Hh];
__device__ float g_q1    [Bb * Hh];
__device__ float g_q2    [Bb * Ss * Hh];
__device__ float g_avec  [Bb * Hh];
__device__ float g_embr  [Vv * Hh];           // tf32-rounded emb
__device__ float g_wr    [212992];            // packed tf32-rounded weights
__device__ float g_bcat  [640];               // packed bias for cat GEMM

// packed weight offsets (floats)
#define WR_CAT 0                  // 640x128 = 81920
#define WR_WIH 81920              // 384x256 = 98304
#define WR_FC1 180224             // 128x128 = 16384
#define WR_FC2 196608             // 128x128 = 16384

// ---------------- tf32 helpers ----------------------------------------------
__device__ __forceinline__ uint32_t f2tf32(float x) {
    uint32_t r;
    asm("cvt.rna.tf32.f32 %0, %1;" : "=r"(r) : "f"(x));
    return r;
}
__device__ __forceinline__ float roundtf(float x) {
    return __uint_as_float(f2tf32(x));
}
__device__ __forceinline__ void mma_tf32(float* c, const uint32_t* a,
                                         const uint32_t* b) {
    asm volatile(
        "mma.sync.aligned.m16n8k8.row.col.f32.tf32.tf32.f32 "
        "{%0,%1,%2,%3}, {%4,%5,%6,%7}, {%8,%9}, {%0,%1,%2,%3};"
        : "+f"(c[0]), "+f"(c[1]), "+f"(c[2]), "+f"(c[3])
        : "r"(a[0]), "r"(a[1]), "r"(a[2]), "r"(a[3]), "r"(b[0]), "r"(b[1]));
}
__device__ __forceinline__ void cp16(uint32_t dst, const void* src, bool pred) {
    int sz = pred ? 16 : 0;
    asm volatile("cp.async.cg.shared.global [%0], [%1], 16, %2;\n"
                 :: "r"(dst), "l"(src), "r"(sz));
}

// ---------------- prep kernels ----------------------------------------------
__global__ void round_kernel(const float* __restrict__ src,
                             float* __restrict__ dst, int n4) {
    int i = blockIdx.x * blockDim.x + threadIdx.x;
    if (i >= n4) return;
    float4 v = ((const float4*)src)[i];
    ((float4*)dst)[i] = make_float4(roundtf(v.x), roundtf(v.y),
                                    roundtf(v.z), roundtf(v.w));
}

// pack [ein_w; eou_w; w_hh] rows (640x128) rounded + bias
__global__ void pack_cat_kernel(const float* __restrict__ ein_w,
                                const float* __restrict__ eou_w,
                                const float* __restrict__ w_hh,
                                const float* __restrict__ ein_b,
                                const float* __restrict__ eou_b,
                                const float* __restrict__ b_hh,
                                float* __restrict__ wcat,
                                float* __restrict__ bcat) {
    int i = blockIdx.x * blockDim.x + threadIdx.x;   // 640*32 float4s
    if (i < 640 * 32) {
        int r = i >> 5, q = i & 31;
        const float* src = (r < 128) ? (ein_w + (size_t)r * Hh)
                         : (r < 256) ? (eou_w + (size_t)(r - 128) * Hh)
                                     : (w_hh + (size_t)(r - 256) * Hh);
        float4 v = ((const float4*)src)[q];
        ((float4*)wcat)[i] = make_float4(roundtf(v.x), roundtf(v.y),
                                         roundtf(v.z), roundtf(v.w));
    }
    if (i < 640) {
        bcat[i] = (i < 128) ? ein_b[i]
                : (i < 256) ? eou_b[i - 128]
                            : b_hh[i - 256];
    }
}

// ---------------- HMMA tf32 GEMM --------------------------------------------
// C[M,N] = A[M,K] @ W[N,K]^T (+bias). Inputs pre-rounded to tf32.
// CTA 128x128, 128 threads = 4 warps (2x2 of 64x64), BK=32, double-buffered.
// M%128==0, K%32==0; N guarded (scalar tail when odd).
#define GBUF 18432
__global__ void __launch_bounds__(128, 2)
gemm2_kernel(const float* __restrict__ A, const float* __restrict__ W,
             const float* __restrict__ bias, float* __restrict__ C,
             int M, int N, int K) {
    extern __shared__ char dsm[];
    const uint32_t sbase = (uint32_t)__cvta_generic_to_shared(dsm);
    const int tid  = threadIdx.x;
    const int warp = tid >> 5, lane = tid & 31;
    const int g  = lane >> 2;
    const int tg = lane & 3;
    const int wm = (warp & 1) * 64;
    const int wn = (warp >> 1) * 64;
    const int m0 = blockIdx.y * 128;
    const int n0 = blockIdx.x * 128;

    float acc[4][8][4];
#pragma unroll
    for (int mt = 0; mt < 4; mt++)
#pragma unroll
        for (int nt = 0; nt < 8; nt++)
#pragma unroll
            for (int i = 0; i < 4; i++) acc[mt][nt][i] = 0.f;

    const int nch = K >> 5;

    auto stage = [&](int c, int s) {
        const int kt = c * 32;
        uint32_t aB = sbase + s * GBUF;
        uint32_t bB = sbase + 2 * GBUF + s * GBUF;
#pragma unroll
        for (int i = 0; i < 4; i++) {
            int idx = tid + i * 128;
#pragma unroll
            for (int h = 0; h < 2; h++) {
                int id2 = idx + h * 512;
                int row = id2 >> 3, q = id2 & 7;
                bool pa = (m0 + row) < M;
                const float* sa = pa ? (A + (size_t)(m0 + row) * K + kt + q * 4) : A;
                cp16(aB + row * 144 + q * 16, sa, pa);
                bool pb = (n0 + row) < N;
                const float* sb = pb ? (W + (size_t)(n0 + row) * K + kt + q * 4) : W;
                cp16(bB + row * 144 + q * 16, sb, pb);
            }
        }
        asm volatile("cp.async.commit_group;\n" ::: "memory");
    };

    stage(0, 0);
    for (int c = 0; c < nch; c++) {
        if (c + 1 < nch) {
            stage(c + 1, (c + 1) & 1);
            asm volatile("cp.async.wait_group 1;" ::: "memory");
        } else {
            asm volatile("cp.async.wait_group 0;" ::: "memory");
        }
        __syncthreads();

        const uint32_t (*sA)[36] =
            (const uint32_t (*)[36])(dsm + (c & 1) * GBUF);
        const uint32_t (*sB)[36] =
            (const uint32_t (*)[36])(dsm + 2 * GBUF + (c & 1) * GBUF);

#pragma unroll
        for (int ks = 0; ks < 4; ks++) {
            const int kk = ks * 8;
            uint32_t af[4][4], bf[8][2];
#pragma unroll
            for (int mt = 0; mt < 4; mt++) {
                int rb = wm + mt * 16;
                af[mt][0] = sA[rb + g][kk + tg];
                af[mt][1] = sA[rb + g + 8][kk + tg];
                af[mt][2] = sA[rb + g][kk + tg + 4];
                af[mt][3] = sA[rb + g + 8][kk + tg + 4];
            }
#pragma unroll
            for (int nt = 0; nt < 8; nt++) {
                int nb = wn + nt * 8;
                bf[nt][0] = sB[nb + g][kk + tg];
                bf[nt][1] = sB[nb + g][kk + tg + 4];
            }
#pragma unroll
            for (int mt = 0; mt < 4; mt++)
#pragma unroll
                for (int nt = 0; nt < 8; nt++)
                    mma_tf32(acc[mt][nt], af[mt], bf[nt]);
        }
        __syncthreads();
    }

    // epilogue
    const bool n_even_full = ((N & 1) == 0);
#pragma unroll
    for (int mt = 0; mt < 4; mt++) {
        int row = m0 + wm + mt * 16 + g;
#pragma unroll
        for (int nt = 0; nt < 8; nt++) {
            int col = n0 + wn + nt * 8 + tg * 2;
            const float* c0 = &acc[mt][nt][0];
            if (n_even_full && col + 1 < N) {
                float b0 = bias ? __ldg(bias + col) : 0.f;
                float b1 = bias ? __ldg(bias + col + 1) : 0.f;
                *(float2*)(C + (size_t)row * N + col) =
                    make_float2(c0[0] + b0, c0[1] + b1);
                *(float2*)(C + (size_t)(row + 8) * N + col) =
                    make_float2(c0[2] + b0, c0[3] + b1);
            } else {
                if (col < N) {
                    float b0 = bias ? __ldg(bias + col) : 0.f;
                    C[(size_t)row * N + col]       = c0[0] + b0;
                    C[(size_t)(row + 8) * N + col] = c0[2] + b0;
                }
                if (col + 1 < N) {
                    float b1 = bias ? __ldg(bias + col + 1) : 0.f;
                    C[(size_t)row * N + col + 1]       = c0[1] + b1;
                    C[(size_t)(row + 8) * N + col + 1] = c0[3] + b1;
                }
            }
        }
    }
}

// ---------------- h = emb[items] (rounded source) ----------------------------
__global__ void gather_kernel(const int* __restrict__ items,
                              const float* __restrict__ embr,
                              float* __restrict__ h, int total4) {
    int i = blockIdx.x * blockDim.x + threadIdx.x;
    if (i >= total4) return;
    int bn = i >> 5, q = i & 31;
    int it = items[bn];
    ((float4*)h)[i] = ((const float4*)embr)[(size_t)it * 32 + q];
}

// ---------------- batched adjacency matmul (2-row register blocking) ---------
// hin/hout live in g_cat (row stride 640): hin at col 0, hout at col 128.
__global__ void amm_kernel(const float* __restrict__ Amat,
                           const float* __restrict__ cat,
                           const float* __restrict__ b_iah,
                           const float* __restrict__ b_oah,
                           float* __restrict__ inputs) {
    int b = blockIdx.x;
    int tid = threadIdx.x;                 // 256 threads
    __shared__ float sA[Nn * Nn];
    __shared__ __align__(16) float sH[Nn * Hh];
    const float* Ab = Amat + (size_t)b * Nn * 2 * Nn;

#pragma unroll
    for (int pass = 0; pass < 2; pass++) {
        const float* bias = pass ? b_oah : b_iah;
        int acol = pass ? Nn : 0;
        for (int i = tid; i < Nn * Nn; i += 256)
            sA[i] = Ab[(i / Nn) * (2 * Nn) + acol + (i % Nn)];
        for (int i = tid; i < Nn * (Hh / 4); i += 256) {
            int k = i >> 5, q = i & 31;
            ((float4*)sH)[i] =
                ((const float4*)cat)[((size_t)b * Nn + k) * 160 + pass * 32 + q];
        }
        __syncthreads();
        // 25 row-pairs x 32 float4 cols = 800 work items
        for (int o = tid; o < 25 * 32; o += 256) {
            int n = o >> 5, q = o & 31;
            float4 bq = *(const float4*)(bias + q * 4);
            float4 a0 = bq, a1 = bq;
#pragma unroll 10
            for (int k = 0; k < Nn; k++) {
                float4 hv = *(const float4*)&sH[k * Hh + q * 4];
                float w0 = sA[n * Nn + k];
                float w1 = sA[(n + 25) * Nn + k];
                a0.x += w0 * hv.x; a0.y += w0 * hv.y;
                a0.z += w0 * hv.z; a0.w += w0 * hv.w;
                a1.x += w1 * hv.x; a1.y += w1 * hv.y;
                a1.z += w1 * hv.z; a1.w += w1 * hv.w;
            }
            a0.x = roundtf(a0.x); a0.y = roundtf(a0.y);
            a0.z = roundtf(a0.z); a0.w = roundtf(a0.w);
            a1.x = roundtf(a1.x); a1.y = roundtf(a1.y);
            a1.z = roundtf(a1.z); a1.w = roundtf(a1.w);
            *(float4*)(inputs + ((size_t)b * Nn + n) * (2 * Hh) + pass * Hh + q * 4) = a0;
            *(float4*)(inputs + ((size_t)b * Nn + n + 25) * (2 * Hh) + pass * Hh + q * 4) = a1;
        }
        __syncthreads();
    }
}

// ---------------- GRU gate math (gh slices live in g_cat) --------------------
__global__ void gru_kernel(const float* __restrict__ gi,
                           const float* __restrict__ cat,
                           const float* __restrict__ h,
                           float* __restrict__ newh, int total) {
    int i = blockIdx.x * blockDim.x + threadIdx.x;
    if (i >= total) return;
    int bn = i / Hh, hh = i - bn * Hh;
    size_t gibase = (size_t)bn * 3 * Hh;
    size_t cbase  = (size_t)bn * 640;
    float i_r = gi[gibase + hh];
    float i_i = gi[gibase + Hh + hh];
    float i_n = gi[gibase + 2 * Hh + hh];
    float h_r = cat[cbase + 256 + hh];
    float h_i = cat[cbase + 384 + hh];
    float h_n = cat[cbase + 512 + hh];
    float r = 1.f / (1.f + expf(-(i_r + h_r)));
    float z = 1.f / (1.f + expf(-(i_i + h_i)));
    float ng = tanhf(i_n + r * h_n);
    newh[i] = roundtf(ng + z * (h[i] - ng));
}

// ---------------- alias gather + ht ------------------------------------------
__global__ void seq_kernel(const int* __restrict__ alias,
                           const int* __restrict__ mask,
                           const float* __restrict__ newh,
                           float* __restrict__ seqh,
                           float* __restrict__ ht) {
    int b = blockIdx.x;
    int tid = threadIdx.x;                 // 256
    __shared__ int sal[Ss];
    __shared__ int slast;
    if (tid < Ss) sal[tid] = alias[b * Ss + tid];
    if (tid == 0) {
        int c = 0;
        for (int s = 0; s < Ss; s++) c += mask[b * Ss + s];
        slast = c - 1;
    }
    __syncthreads();
    const float4* src = (const float4*)newh + (size_t)b * Nn * (Hh / 4);
    float4* dst = (float4*)seqh + (size_t)b * Ss * (Hh / 4);
    for (int i = tid; i < Ss * (Hh / 4); i += 256) {
        int s = i >> 5, q = i & 31;
        dst[i] = src[sal[s] * 32 + q];
    }
    if (tid < 32) {
        const float4* hrow = (const float4*)newh + ((size_t)b * Nn + sal[slast]) * (Hh / 4);
        ((float4*)ht)[(size_t)b * (Hh / 4) + tid] = hrow[tid];
    }
}

// ---------------- attention readout ------------------------------------------
__global__ void attn_kernel(const float* __restrict__ q1,
                            const float* __restrict__ q2,
                            const float* __restrict__ fc3_w,
                            const float* __restrict__ seqh,
                            const int* __restrict__ mask,
                            float* __restrict__ avec) {
    int b = blockIdx.x;
    int tid = threadIdx.x;                 // 128
    int warp = tid >> 5, lane = tid & 31;
    __shared__ float salpha[Ss];
    for (int s = warp; s < Ss; s += 4) {
        float part = 0.f;
        for (int hh = lane; hh < Hh; hh += 32) {
            float v = q1[(size_t)b * Hh + hh] + q2[((size_t)b * Ss + s) * Hh + hh];
            part += fc3_w[hh] / (1.f + expf(-v));
        }
#pragma unroll
        for (int off = 16; off; off >>= 1)
            part += __shfl_down_sync(0xffffffffu, part, off);
        if (lane == 0) salpha[s] = part;
    }
    __syncthreads();
    int hh = tid;
    float acc = 0.f;
    for (int s = 0; s < Ss; s++) {
        float m = (float)mask[b * Ss + s];
        acc += salpha[s] * seqh[((size_t)b * Ss + s) * Hh + hh] * m;
    }
    avec[(size_t)b * Hh + hh] = roundtf(acc);
}

// ---------------- launch -----------------------------------------------------
extern "C" void kernel_launch(void* const* d_in, const int* in_sizes, int n_in,
                              void* d_out, int out_size) {
    const int*   alias_inputs = (const int*)  d_in[0];
    const float* A            = (const float*)d_in[1];
    const int*   items        = (const int*)  d_in[2];
    const int*   mask         = (const int*)  d_in[3];
    const float* emb          = (const float*)d_in[4];
    const float* ein_w        = (const float*)d_in[5];
    const float* ein_b        = (const float*)d_in[6];
    const float* eou_w        = (const float*)d_in[7];
    const float* eou_b        = (const float*)d_in[8];
    const float* w_ih         = (const float*)d_in[9];
    const float* w_hh         = (const float*)d_in[10];
    const float* b_ih         = (const float*)d_in[11];
    const float* b_hh         = (const float*)d_in[12];
    const float* b_iah        = (const float*)d_in[13];
    const float* b_oah        = (const float*)d_in[14];
    const float* fc1_w        = (const float*)d_in[15];
    const float* fc1_b        = (const float*)d_in[16];
    const float* fc2_w        = (const float*)d_in[17];
    const float* fc2_b        = (const float*)d_in[18];
    const float* fc3_w        = (const float*)d_in[19];
    float* out = (float*)d_out;

    cudaFuncSetAttribute(gemm2_kernel,
                         cudaFuncAttributeMaxDynamicSharedMemorySize, 4 * GBUF);

    float *p_h, *p_cat, *p_inputs, *p_gi, *p_newh;
    float *p_seqh, *p_ht, *p_q1, *p_q2, *p_avec, *p_embr, *p_wr, *p_bcat;
    cudaGetSymbolAddress((void**)&p_h,      g_h);
    cudaGetSymbolAddress((void**)&p_cat,    g_cat);
    cudaGetSymbolAddress((void**)&p_inputs, g_inputs);
    cudaGetSymbolAddress((void**)&p_gi,     g_gi);
    cudaGetSymbolAddress((void**)&p_newh,   g_newh);
    cudaGetSymbolAddress((void**)&p_seqh,   g_seqh);
    cudaGetSymbolAddress((void**)&p_ht,     g_ht);
    cudaGetSymbolAddress((void**)&p_q1,     g_q1);
    cudaGetSymbolAddress((void**)&p_q2,     g_q2);
    cudaGetSymbolAddress((void**)&p_avec,   g_avec);
    cudaGetSymbolAddress((void**)&p_embr,   g_embr);
    cudaGetSymbolAddress((void**)&p_wr,     g_wr);
    cudaGetSymbolAddress((void**)&p_bcat,   g_bcat);

    const int BN = Bb * Nn;                // 51200 = 400 * 128
    const int SM = 4 * GBUF;

    // 0. prep: round emb, pack cat weights, round others
    {
        int n4 = Vv * Hh / 4;
        round_kernel<<<(n4 + 255) / 256, 256>>>(emb, p_embr, n4);
        pack_cat_kernel<<<(640 * 32 + 255) / 256, 256>>>(
            ein_w, eou_w, w_hh, ein_b, eou_b, b_hh, p_wr + WR_CAT, p_bcat);
        round_kernel<<<(98304 / 4 + 255) / 256, 256>>>(w_ih,  p_wr + WR_WIH, 98304 / 4);
        round_kernel<<<(16384 / 4 + 255) / 256, 256>>>(fc1_w, p_wr + WR_FC1, 16384 / 4);
        round_kernel<<<(16384 / 4 + 255) / 256, 256>>>(fc2_w, p_wr + WR_FC2, 16384 / 4);
    }
    // 1. gather
    {
        int total4 = BN * (Hh / 4);
        gather_kernel<<<(total4 + 255) / 256, 256>>>(items, p_embr, p_h, total4);
    }
    // 2. cat GEMM: [hin|hout|gh] = h @ [ein;eou;whh]^T  (M=51200, N=640, K=128)
    gemm2_kernel<<<dim3(5, BN / 128), 128, SM>>>(p_h, p_wr + WR_CAT, p_bcat,
                                                 p_cat, BN, 640, Hh);
    // 3. adjacency matmuls
    amm_kernel<<<Bb, 256>>>(A, p_cat, b_iah, b_oah, p_inputs);
    // 4. gi  (N=384, K=256)
    gemm2_kernel<<<dim3(3, BN / 128), 128, SM>>>(p_inputs, p_wr + WR_WIH, b_ih,
                                                 p_gi, BN, 3 * Hh, 2 * Hh);
    // 5. GRU
    {
        int total = BN * Hh;
        gru_kernel<<<(total + 255) / 256, 256>>>(p_gi, p_cat, p_h, p_newh, total);
    }
    // 6. seq gather + ht
    seq_kernel<<<Bb, 256>>>(alias_inputs, mask, p_newh, p_seqh, p_ht);
    // 7. q1 (M=1024, N=128, K=128)
    gemm2_kernel<<<dim3(1, Bb / 128), 128, SM>>>(p_ht, p_wr + WR_FC1, fc1_b,
                                                 p_q1, Bb, Hh, Hh);
    // 8. q2 (M=51200, N=128, K=128)
    gemm2_kernel<<<dim3(1, BN / 128), 128, SM>>>(p_seqh, p_wr + WR_FC2, fc2_b,
                                                 p_q2, Bb * Ss, Hh, Hh);
    // 9. attention
    attn_kernel<<<Bb, 128>>>(p_q1, p_q2, fc3_w, p_seqh, mask, p_avec);
    // 10. out = a @ emb[1:].T  (M=1024, N=99999, K=128)
    {
        int Nout = Vv - 1;
        gemm2_kernel<<<dim3((Nout + 127) / 128, Bb / 128), 128, SM>>>(
            p_avec, p_embr + Hh, nullptr, out, Bb, Nout, Hh);
    }
    (void)in_sizes; (void)n_in; (void)out_size;
}